// round 5
// baseline (speedup 1.0000x reference)
#include <cuda_runtime.h>
#include <cuda_bf16.h>
#include <cstdint>
#include <math.h>

// ---------------------------------------------------------------------------
// Problem constants
// ---------------------------------------------------------------------------
#define D        256
#define NROWS    8192
#define LOG_NORM 2.0767937f     // -0.5*ln(2*pi) - ln(0.05)
#define HALF_INV_SIG2 200.0f

// int8 screen: q = round(127*v). dot_int = 16129*cos + err, err_std ~ 3.2e-3*16129.
// fp32 exp underflows for cos < 0.2745; screen at 0.24 -> 10 sigma of safety.
#define SCREEN_INT 3871          // 0.24 * 127 * 127

#define TILE_N   128             // Ex rows per CTA (MMA M dim)
#define TILE_M   256             // Ey rows per CTA (MMA N dim)
#define BK       128             // s8 k per chunk = 128 bytes/row
#define NCHUNK   (D / BK)        // 2
#define NT       256             // 8 warps

#define CAP      (1 << 20)

// Scratch (device globals per harness rules)
__device__ float g_xn[(size_t)NROWS * D];     // normalized fp32
__device__ float g_yn[(size_t)NROWS * D];
__device__ int   g_xq[(size_t)NROWS * (D/4)]; // normalized int8 (packed 4/int)
__device__ int   g_yq[(size_t)NROWS * (D/4)];
__device__ int   g_cnt;
__device__ int2  g_pairs[CAP];

// ---------------------------------------------------------------------------
// Helpers
// ---------------------------------------------------------------------------
__device__ __forceinline__ uint32_t smem_u32(const void* p) {
    uint32_t a;
    asm("{ .reg .u64 t; cvta.to.shared.u64 t, %1; cvt.u32.u64 %0, t; }" : "=r"(a) : "l"(p));
    return a;
}
#define SWZ(x) ((x) ^ (((x) >> 3) & 0x70))

__device__ __forceinline__ void cp16(uint32_t s, const void* g) {
    uint64_t ga;
    asm("cvta.to.global.u64 %0, %1;" : "=l"(ga) : "l"(g));
    asm volatile("cp.async.cg.shared.global [%0], [%1], 16;" :: "r"(s), "l"(ga) : "memory");
}
#define CP_COMMIT() asm volatile("cp.async.commit_group;" ::: "memory")
#define CP_WAIT(n)  asm volatile("cp.async.wait_group %0;" :: "n"(n) : "memory")

#define LDSM4(r, addr) \
    asm volatile("ldmatrix.sync.aligned.m8n8.x4.shared.b16 {%0,%1,%2,%3}, [%4];" \
        : "=r"((r)[0]), "=r"((r)[1]), "=r"((r)[2]), "=r"((r)[3]) : "r"(addr))

// int8 IMMA: m16n8k32, s32 accumulate (exact)
#define MMA16832(ac, a, b0, b1) \
    asm volatile("mma.sync.aligned.m16n8k32.row.col.s32.s8.s8.s32 " \
        "{%0,%1,%2,%3},{%4,%5,%6,%7},{%8,%9},{%0,%1,%2,%3};" \
        : "+r"((ac)[0]), "+r"((ac)[1]), "+r"((ac)[2]), "+r"((ac)[3]) \
        : "r"((a)[0]), "r"((a)[1]), "r"((a)[2]), "r"((a)[3]), "r"(b0), "r"(b1))

// SMEM layout: 2 chunks resident simultaneously, A[128][128B] + B[256][128B] each
#define A_BYTES     (TILE_N * 128)            // 16384
#define B_BYTES     (TILE_M * 128)            // 32768
#define STAGE_BYTES (A_BYTES + B_BYTES)       // 49152
#define SM_A(s)     ((s) * STAGE_BYTES)
#define SM_B(s)     (SM_A(s) + A_BYTES)
#define SMEM_TOTAL  (2 * STAGE_BYTES)         // 98304

// ---------------------------------------------------------------------------
// Normalize rows -> fp32 + packed int8 copies. One warp per row. Resets g_cnt.
// ---------------------------------------------------------------------------
__global__ void __launch_bounds__(256) normsplit_kernel(
    const float* __restrict__ Ex, const float* __restrict__ Ey, int N, int M)
{
    if (blockIdx.x == 0 && threadIdx.x == 0) g_cnt = 0;

    int warp = threadIdx.x >> 5, lane = threadIdx.x & 31;
    int row = blockIdx.x * 8 + warp;
    if (row >= N + M) return;

    const float* src; float* dstf; int* dstq; int r;
    if (row < N) { src = Ex; dstf = g_xn; dstq = g_xq; r = row; }
    else         { src = Ey; dstf = g_yn; dstq = g_yq; r = row - N; }

    const float4* s4 = reinterpret_cast<const float4*>(src + (size_t)r * D);
    float4 v0 = s4[lane];
    float4 v1 = s4[lane + 32];

    float ss = v0.x*v0.x + v0.y*v0.y + v0.z*v0.z + v0.w*v0.w
             + v1.x*v1.x + v1.y*v1.y + v1.z*v1.z + v1.w*v1.w;
    #pragma unroll
    for (int off = 16; off > 0; off >>= 1)
        ss += __shfl_xor_sync(0xFFFFFFFFu, ss, off);
    float inv = 1.0f / fmaxf(sqrtf(ss), 1e-8f);

    v0.x *= inv; v0.y *= inv; v0.z *= inv; v0.w *= inv;
    v1.x *= inv; v1.y *= inv; v1.z *= inv; v1.w *= inv;

    float4* d4 = reinterpret_cast<float4*>(dstf + (size_t)r * D);
    d4[lane]      = v0;
    d4[lane + 32] = v1;

    // Pack int8: q = round(127*v), 4 per int
    int* dq = dstq + (size_t)r * (D/4);
    {
        int a = __float2int_rn(v0.x * 127.0f), b = __float2int_rn(v0.y * 127.0f);
        int c = __float2int_rn(v0.z * 127.0f), d = __float2int_rn(v0.w * 127.0f);
        dq[lane] = (a & 0xFF) | ((b & 0xFF) << 8) | ((c & 0xFF) << 16) | (d << 24);
    }
    {
        int a = __float2int_rn(v1.x * 127.0f), b = __float2int_rn(v1.y * 127.0f);
        int c = __float2int_rn(v1.z * 127.0f), d = __float2int_rn(v1.w * 127.0f);
        dq[lane + 32] = (a & 0xFF) | ((b & 0xFF) << 8) | ((c & 0xFF) << 16) | (d << 24);
    }
}

// ---------------------------------------------------------------------------
// Screen: int8 IMMA GEMM (mma.sync.m16n8k32.s8), emit pairs dot_int > SCREEN_INT.
// CTA 128(n) x 256(m); 8 warps, warp tile 64x64; K=256 s8 in 2 chunks of 128.
// Both chunks prefetched up front (no steady-state pipeline).
// ---------------------------------------------------------------------------
__global__ void __launch_bounds__(NT, 1) screen_kernel()
{
    extern __shared__ __align__(1024) char smem[];
    const uint32_t sb = smem_u32(smem);
    const int t = threadIdx.x;
    const int wid = t >> 5, lane = t & 31;
    const int nBase = blockIdx.y * TILE_N;
    const int mBase = blockIdx.x * TILE_M;
    const int nOff = (wid >> 2) * 64;     // warp n offset in tile
    const int mOff = (wid & 3) * 64;      // warp m offset in tile

    const char* Xp = (const char*)g_xq + (size_t)nBase * D;   // 256 B/row
    const char* Yp = (const char*)g_yq + (size_t)mBase * D;

    int acc[4][8][4];
    #pragma unroll
    for (int mi = 0; mi < 4; mi++)
        #pragma unroll
        for (int j = 0; j < 8; j++)
            #pragma unroll
            for (int r = 0; r < 4; r++) acc[mi][j][r] = 0;

    // Prefetch both chunks (c = byte offset c*128 within the 256B row)
    #pragma unroll
    for (int c = 0; c < NCHUNK; c++) {
        int bkb = c * 128;
        #pragma unroll
        for (int i = 0; i < 4; i++) {     // A: 128 rows x 128B = 1024 x 16B
            int idx = t + 256 * i; int r = idx >> 3; int kb = (idx & 7) * 16;
            cp16(sb + SM_A(c) + SWZ(r * 128 + kb), Xp + (size_t)r * 256 + bkb + kb);
        }
        #pragma unroll
        for (int i = 0; i < 8; i++) {     // B: 256 rows x 128B = 2048 x 16B
            int idx = t + 256 * i; int r = idx >> 3; int kb = (idx & 7) * 16;
            cp16(sb + SM_B(c) + SWZ(r * 128 + kb), Yp + (size_t)r * 256 + bkb + kb);
        }
    }
    CP_COMMIT();
    CP_WAIT(0);
    __syncthreads();

    // ldmatrix lane addressing: lanes 0-15 -> rows (lower/upper 8), lanes 16-31 -> +16B k
    const int lrow = (lane & 7) + ((lane >> 3) & 1) * 8;
    const int lkb  = (lane >> 4) * 16;

    #pragma unroll
    for (int c = 0; c < NCHUNK; c++) {
        #pragma unroll
        for (int kk = 0; kk < 4; kk++) {          // 4 x k32 per 128B chunk
            uint32_t af[4][4], bf[4][4];
            #pragma unroll
            for (int mi = 0; mi < 4; mi++) {
                uint32_t addr = sb + SM_A(c)
                    + SWZ((nOff + mi * 16 + lrow) * 128 + kk * 32 + lkb);
                LDSM4(af[mi], addr);
            }
            #pragma unroll
            for (int nj = 0; nj < 4; nj++) {
                uint32_t addr = sb + SM_B(c)
                    + SWZ((mOff + nj * 16 + lrow) * 128 + kk * 32 + lkb);
                LDSM4(bf[nj], addr);
            }
            #pragma unroll
            for (int mi = 0; mi < 4; mi++)
                #pragma unroll
                for (int nj = 0; nj < 4; nj++) {
                    MMA16832(acc[mi][2*nj],     af[mi], bf[nj][0], bf[nj][2]);
                    MMA16832(acc[mi][2*nj + 1], af[mi], bf[nj][1], bf[nj][3]);
                }
        }
    }

    // Emit candidates. c-frag: r0/r1 -> row lane>>2, cols 2(lane&3)+{0,1};
    //                  r2/r3 -> row (lane>>2)+8, same cols.
    const int rBase = nBase + nOff + (lane >> 2);
    const int cBase = mBase + mOff + 2 * (lane & 3);
    #pragma unroll
    for (int mi = 0; mi < 4; mi++)
        #pragma unroll
        for (int j = 0; j < 8; j++)
            #pragma unroll
            for (int r = 0; r < 4; r++) {
                if (acc[mi][j][r] > SCREEN_INT) {
                    int n = rBase + mi * 16 + ((r >> 1) ? 8 : 0);
                    int m = cBase + j * 8 + (r & 1);
                    int idx = atomicAdd(&g_cnt, 1);
                    if (idx < CAP) g_pairs[idx] = make_int2(n, m);
                }
            }
}

// ---------------------------------------------------------------------------
// Exact fp32 recompute of candidates: dot + expf + atomicAdd. 1 warp/pair.
// ---------------------------------------------------------------------------
__global__ void __launch_bounds__(256) recompute_kernel(float* __restrict__ out)
{
    int lane = threadIdx.x & 31;
    int w    = (blockIdx.x * blockDim.x + threadIdx.x) >> 5;
    int nw   = (gridDim.x * blockDim.x) >> 5;
    int cnt  = *(volatile int*)&g_cnt;
    if (cnt > CAP) cnt = CAP;

    for (int i = w; i < cnt; i += nw) {
        int2 p = g_pairs[i];
        const float4* x = reinterpret_cast<const float4*>(g_xn + (size_t)p.x * D);
        const float4* y = reinterpret_cast<const float4*>(g_yn + (size_t)p.y * D);
        float4 xa = x[lane], xb = x[lane + 32];
        float4 ya = y[lane], yb = y[lane + 32];
        float s = xa.x*ya.x + xa.y*ya.y + xa.z*ya.z + xa.w*ya.w
                + xb.x*yb.x + xb.y*yb.y + xb.z*yb.z + xb.w*yb.w;
        #pragma unroll
        for (int off = 16; off > 0; off >>= 1)
            s += __shfl_xor_sync(0xFFFFFFFFu, s, off);
        if (lane == 0) {
            float dd = s - 1.0f;
            float e = expf(LOG_NORM - HALF_INV_SIG2 * dd * dd);
            if (e != 0.0f) atomicAdd(&out[p.y], e);
        }
    }
}

// ---------------------------------------------------------------------------
extern "C" void kernel_launch(void* const* d_in, const int* in_sizes, int n_in,
                              void* d_out, int out_size)
{
    const float* Ex = (const float*)d_in[0];
    const float* Ey = (const float*)d_in[1];
    float* out = (float*)d_out;

    int N = in_sizes[0] / D;   // 8192
    int M = in_sizes[1] / D;   // 8192

    cudaFuncSetAttribute(screen_kernel,
                         cudaFuncAttributeMaxDynamicSharedMemorySize, SMEM_TOTAL);

    cudaMemsetAsync(out, 0, (size_t)out_size * sizeof(float));

    normsplit_kernel<<<(N + M + 7) / 8, 256>>>(Ex, Ey, N, M);

    dim3 grid(M / TILE_M, N / TILE_N);
    screen_kernel<<<grid, NT, SMEM_TOTAL>>>();

    recompute_kernel<<<64, 256>>>(out);
}

// round 6
// speedup vs baseline: 1.2436x; 1.2436x over previous
#include <cuda_runtime.h>
#include <cuda_bf16.h>
#include <cuda_fp8.h>
#include <cstdint>
#include <math.h>

// ---------------------------------------------------------------------------
// Problem constants
// ---------------------------------------------------------------------------
#define D        256
#define NROWS    8192
#define LOG_NORM 2.0767937f     // -0.5*ln(2*pi) - ln(0.05)
#define HALF_INV_SIG2 200.0f

// e4m3 screen: dot err std ~5e-3; fp32 exp underflows below cos~0.2745.
// Threshold 0.22 -> ~11 sigma of safety margin.
#define SCREEN_T 0.22f

#define TILE_N   128             // Ex rows per CTA (MMA M dim)
#define TILE_M   256             // Ey rows per CTA (MMA N dim)
#define NPLANE   2               // K=256 e4m3 = 2 planes of 128 B/row
#define NT       256             // 8 warps

#define CAP      (1 << 20)

// Scratch (device globals per harness rules)
__device__ float g_xn[(size_t)NROWS * D];     // normalized fp32
__device__ float g_yn[(size_t)NROWS * D];
__device__ int   g_xq[(size_t)NROWS * (D/4)]; // normalized e4m3 (packed 4/int)
__device__ int   g_yq[(size_t)NROWS * (D/4)];
__device__ int   g_cnt;
__device__ int2  g_pairs[CAP];

// ---------------------------------------------------------------------------
// Helpers
// ---------------------------------------------------------------------------
__device__ __forceinline__ uint32_t smem_u32(const void* p) {
    uint32_t a;
    asm("{ .reg .u64 t; cvta.to.shared.u64 t, %1; cvt.u32.u64 %0, t; }" : "=r"(a) : "l"(p));
    return a;
}
#define SWZ(x) ((x) ^ (((x) >> 3) & 0x70))

__device__ __forceinline__ void cp16(uint32_t s, const void* g) {
    uint64_t ga;
    asm("cvta.to.global.u64 %0, %1;" : "=l"(ga) : "l"(g));
    asm volatile("cp.async.cg.shared.global [%0], [%1], 16;" :: "r"(s), "l"(ga) : "memory");
}
#define CP_COMMIT() asm volatile("cp.async.commit_group;" ::: "memory")
#define CP_WAIT(n)  asm volatile("cp.async.wait_group %0;" :: "n"(n) : "memory")

#define LDSM4(r, addr) \
    asm volatile("ldmatrix.sync.aligned.m8n8.x4.shared.b16 {%0,%1,%2,%3}, [%4];" \
        : "=r"((r)[0]), "=r"((r)[1]), "=r"((r)[2]), "=r"((r)[3]) : "r"(addr))

// e4m3 FP8 MMA: m16n8k32, f32 accumulate (sm_89+ PTX, Blackwell-fast)
#define MMAFP8(ac, a, b0, b1) \
    asm volatile("mma.sync.aligned.m16n8k32.row.col.f32.e4m3.e4m3.f32 " \
        "{%0,%1,%2,%3},{%4,%5,%6,%7},{%8,%9},{%0,%1,%2,%3};" \
        : "+f"((ac)[0]), "+f"((ac)[1]), "+f"((ac)[2]), "+f"((ac)[3]) \
        : "r"((a)[0]), "r"((a)[1]), "r"((a)[2]), "r"((a)[3]), "r"(b0), "r"(b1))

// SMEM: 2 K-planes resident, each A[128][128B] + B[256][128B]
#define A_BYTES     (TILE_N * 128)            // 16384
#define B_BYTES     (TILE_M * 128)            // 32768
#define PLANE_BYTES (A_BYTES + B_BYTES)       // 49152
#define SM_A(c)     ((c) * PLANE_BYTES)
#define SM_B(c)     (SM_A(c) + A_BYTES)
#define SMEM_TOTAL  (NPLANE * PLANE_BYTES)    // 98304

// Pack 4 floats -> 4 e4m3 bytes. Pair-order inside fp8x2 is applied
// identically to both operands, so any swap cancels in the dot product.
__device__ __forceinline__ int pack4_e4m3(float a, float b, float c, float d) {
    unsigned lo = (unsigned)__nv_cvt_float2_to_fp8x2(make_float2(a, b),
                                                     __NV_SATFINITE, __NV_E4M3);
    unsigned hi = (unsigned)__nv_cvt_float2_to_fp8x2(make_float2(c, d),
                                                     __NV_SATFINITE, __NV_E4M3);
    return (int)(lo | (hi << 16));
}

// ---------------------------------------------------------------------------
// Normalize rows -> fp32 + packed e4m3 copies. One warp per row. Resets g_cnt.
// ---------------------------------------------------------------------------
__global__ void __launch_bounds__(256) normsplit_kernel(
    const float* __restrict__ Ex, const float* __restrict__ Ey, int N, int M)
{
    if (blockIdx.x == 0 && threadIdx.x == 0) g_cnt = 0;

    int warp = threadIdx.x >> 5, lane = threadIdx.x & 31;
    int row = blockIdx.x * 8 + warp;
    if (row >= N + M) return;

    const float* src; float* dstf; int* dstq; int r;
    if (row < N) { src = Ex; dstf = g_xn; dstq = g_xq; r = row; }
    else         { src = Ey; dstf = g_yn; dstq = g_yq; r = row - N; }

    const float4* s4 = reinterpret_cast<const float4*>(src + (size_t)r * D);
    float4 v0 = s4[lane];
    float4 v1 = s4[lane + 32];

    float ss = v0.x*v0.x + v0.y*v0.y + v0.z*v0.z + v0.w*v0.w
             + v1.x*v1.x + v1.y*v1.y + v1.z*v1.z + v1.w*v1.w;
    #pragma unroll
    for (int off = 16; off > 0; off >>= 1)
        ss += __shfl_xor_sync(0xFFFFFFFFu, ss, off);
    float inv = 1.0f / fmaxf(sqrtf(ss), 1e-8f);

    v0.x *= inv; v0.y *= inv; v0.z *= inv; v0.w *= inv;
    v1.x *= inv; v1.y *= inv; v1.z *= inv; v1.w *= inv;

    float4* d4 = reinterpret_cast<float4*>(dstf + (size_t)r * D);
    d4[lane]      = v0;
    d4[lane + 32] = v1;

    int* dq = dstq + (size_t)r * (D/4);
    dq[lane]      = pack4_e4m3(v0.x, v0.y, v0.z, v0.w);
    dq[lane + 32] = pack4_e4m3(v1.x, v1.y, v1.z, v1.w);
}

// ---------------------------------------------------------------------------
// Screen: e4m3 FP8 MMA GEMM, emit pairs with cos_fp8 > 0.22.
// CTA 128(n) x 256(m); 8 warps, warp tile 64x64; K=256 e4m3 in 2 planes.
// Plane 1 load overlaps plane 0 compute (2 cp.async commit groups).
// ---------------------------------------------------------------------------
__global__ void __launch_bounds__(NT, 1) screen_kernel()
{
    extern __shared__ __align__(1024) char smem[];
    const uint32_t sb = smem_u32(smem);
    const int t = threadIdx.x;
    const int wid = t >> 5, lane = t & 31;
    const int nBase = blockIdx.y * TILE_N;
    const int mBase = blockIdx.x * TILE_M;
    const int nOff = (wid >> 2) * 64;     // warp n offset in tile
    const int mOff = (wid & 3) * 64;      // warp m offset in tile

    const char* Xp = (const char*)g_xq + (size_t)nBase * D;   // 256 B/row
    const char* Yp = (const char*)g_yq + (size_t)mBase * D;

    float acc[4][8][4];
    #pragma unroll
    for (int mi = 0; mi < 4; mi++)
        #pragma unroll
        for (int j = 0; j < 8; j++)
            #pragma unroll
            for (int r = 0; r < 4; r++) acc[mi][j][r] = 0.0f;

    // Issue both planes as separate commit groups (in-order completion)
    #pragma unroll
    for (int c = 0; c < NPLANE; c++) {
        int bkb = c * 128;
        #pragma unroll
        for (int i = 0; i < 4; i++) {     // A: 128 rows x 128B
            int idx = t + 256 * i; int r = idx >> 3; int kb = (idx & 7) * 16;
            cp16(sb + SM_A(c) + SWZ(r * 128 + kb), Xp + (size_t)r * 256 + bkb + kb);
        }
        #pragma unroll
        for (int i = 0; i < 8; i++) {     // B: 256 rows x 128B
            int idx = t + 256 * i; int r = idx >> 3; int kb = (idx & 7) * 16;
            cp16(sb + SM_B(c) + SWZ(r * 128 + kb), Yp + (size_t)r * 256 + bkb + kb);
        }
        CP_COMMIT();
    }

    // ldmatrix lane addressing (HW-verified in R5's s8 run; byte-identical)
    const int lrow = (lane & 7) + ((lane >> 3) & 1) * 8;
    const int lkb  = (lane >> 4) * 16;

    #pragma unroll
    for (int c = 0; c < NPLANE; c++) {
        if (c == 0) CP_WAIT(1); else CP_WAIT(0);
        __syncthreads();

        #pragma unroll
        for (int kk = 0; kk < 4; kk++) {          // 4 x k32 per 128B plane
            uint32_t af[4][4], bf[4][4];
            #pragma unroll
            for (int mi = 0; mi < 4; mi++) {
                uint32_t addr = sb + SM_A(c)
                    + SWZ((nOff + mi * 16 + lrow) * 128 + kk * 32 + lkb);
                LDSM4(af[mi], addr);
            }
            #pragma unroll
            for (int nj = 0; nj < 4; nj++) {
                uint32_t addr = sb + SM_B(c)
                    + SWZ((mOff + nj * 16 + lrow) * 128 + kk * 32 + lkb);
                LDSM4(bf[nj], addr);
            }
            #pragma unroll
            for (int mi = 0; mi < 4; mi++)
                #pragma unroll
                for (int nj = 0; nj < 4; nj++) {
                    MMAFP8(acc[mi][2*nj],     af[mi], bf[nj][0], bf[nj][2]);
                    MMAFP8(acc[mi][2*nj + 1], af[mi], bf[nj][1], bf[nj][3]);
                }
        }
    }

    // Emit candidates. c-frag: r0/r1 -> row lane>>2, cols 2(lane&3)+{0,1};
    //                  r2/r3 -> row (lane>>2)+8, same cols.
    const int rBase = nBase + nOff + (lane >> 2);
    const int cBase = mBase + mOff + 2 * (lane & 3);
    #pragma unroll
    for (int mi = 0; mi < 4; mi++)
        #pragma unroll
        for (int j = 0; j < 8; j++)
            #pragma unroll
            for (int r = 0; r < 4; r++) {
                if (acc[mi][j][r] > SCREEN_T) {
                    int n = rBase + mi * 16 + ((r >> 1) ? 8 : 0);
                    int m = cBase + j * 8 + (r & 1);
                    int idx = atomicAdd(&g_cnt, 1);
                    if (idx < CAP) g_pairs[idx] = make_int2(n, m);
                }
            }
}

// ---------------------------------------------------------------------------
// Exact fp32 recompute of candidates: dot + expf + atomicAdd. 1 warp/pair.
// ---------------------------------------------------------------------------
__global__ void __launch_bounds__(256) recompute_kernel(float* __restrict__ out)
{
    int lane = threadIdx.x & 31;
    int w    = (blockIdx.x * blockDim.x + threadIdx.x) >> 5;
    int nw   = (gridDim.x * blockDim.x) >> 5;
    int cnt  = *(volatile int*)&g_cnt;
    if (cnt > CAP) cnt = CAP;

    for (int i = w; i < cnt; i += nw) {
        int2 p = g_pairs[i];
        const float4* x = reinterpret_cast<const float4*>(g_xn + (size_t)p.x * D);
        const float4* y = reinterpret_cast<const float4*>(g_yn + (size_t)p.y * D);
        float4 xa = x[lane], xb = x[lane + 32];
        float4 ya = y[lane], yb = y[lane + 32];
        float s = xa.x*ya.x + xa.y*ya.y + xa.z*ya.z + xa.w*ya.w
                + xb.x*yb.x + xb.y*yb.y + xb.z*yb.z + xb.w*yb.w;
        #pragma unroll
        for (int off = 16; off > 0; off >>= 1)
            s += __shfl_xor_sync(0xFFFFFFFFu, s, off);
        if (lane == 0) {
            float dd = s - 1.0f;
            float e = expf(LOG_NORM - HALF_INV_SIG2 * dd * dd);
            if (e != 0.0f) atomicAdd(&out[p.y], e);
        }
    }
}

// ---------------------------------------------------------------------------
extern "C" void kernel_launch(void* const* d_in, const int* in_sizes, int n_in,
                              void* d_out, int out_size)
{
    const float* Ex = (const float*)d_in[0];
    const float* Ey = (const float*)d_in[1];
    float* out = (float*)d_out;

    int N = in_sizes[0] / D;   // 8192
    int M = in_sizes[1] / D;   // 8192

    cudaFuncSetAttribute(screen_kernel,
                         cudaFuncAttributeMaxDynamicSharedMemorySize, SMEM_TOTAL);

    cudaMemsetAsync(out, 0, (size_t)out_size * sizeof(float));

    normsplit_kernel<<<(N + M + 7) / 8, 256>>>(Ex, Ey, N, M);

    dim3 grid(M / TILE_M, N / TILE_N);
    screen_kernel<<<grid, NT, SMEM_TOTAL>>>();

    recompute_kernel<<<64, 256>>>(out);
}

// round 7
// speedup vs baseline: 2.4380x; 1.9604x over previous
#include <cuda_runtime.h>
#include <cuda_fp16.h>
#include <cstdint>
#include <math.h>

// ---------------------------------------------------------------------------
// Problem constants
// ---------------------------------------------------------------------------
#define D        256
#define NROWS    8192
#define LOG_NORM 2.0767937f     // -0.5*ln(2*pi) - ln(0.05)
#define HALF_INV_SIG2 200.0f

// f16 screen: accum err ~1-2e-3 rms; fp32 exp underflows below cos~0.2745.
// Threshold 0.24 -> ~0.035 margin (~20 sigma).
#define SCREEN_T 0.24f

#define TILE_N   128             // Ex rows per CTA (MMA M dim)
#define TILE_M   256             // Ey rows per CTA (MMA N dim)
#define BKB      128             // bytes of K per chunk (64 f16)
#define NCHUNK   4               // K=256 f16 = 512 B/row = 4 chunks
#define NT       512             // 16 warps

#define CAP      (1 << 20)

// Scratch (device globals per harness rules)
__device__ float    g_xn[(size_t)NROWS * D];      // normalized fp32
__device__ float    g_yn[(size_t)NROWS * D];
__device__ unsigned g_xh[(size_t)NROWS * (D/2)];  // normalized f16 (packed 2/u32)
__device__ unsigned g_yh[(size_t)NROWS * (D/2)];
__device__ int      g_cnt;
__device__ int2     g_pairs[CAP];

// ---------------------------------------------------------------------------
// Helpers
// ---------------------------------------------------------------------------
__device__ __forceinline__ uint32_t smem_u32(const void* p) {
    uint32_t a;
    asm("{ .reg .u64 t; cvta.to.shared.u64 t, %1; cvt.u32.u64 %0, t; }" : "=r"(a) : "l"(p));
    return a;
}
#define SWZ(x) ((x) ^ (((x) >> 3) & 0x70))

__device__ __forceinline__ void cp16(uint32_t s, const void* g) {
    uint64_t ga;
    asm("cvta.to.global.u64 %0, %1;" : "=l"(ga) : "l"(g));
    asm volatile("cp.async.cg.shared.global [%0], [%1], 16;" :: "r"(s), "l"(ga) : "memory");
}
#define CP_COMMIT() asm volatile("cp.async.commit_group;" ::: "memory")
#define CP_WAIT(n)  asm volatile("cp.async.wait_group %0;" :: "n"(n) : "memory")

#define LDSM4(r, addr) \
    asm volatile("ldmatrix.sync.aligned.m8n8.x4.shared.b16 {%0,%1,%2,%3}, [%4];" \
        : "=r"((r)[0]), "=r"((r)[1]), "=r"((r)[2]), "=r"((r)[3]) : "r"(addr))

// f16-accumulate HMMA: m16n8k16, D/C = 2 x .f16x2 regs (2x rate vs f32 accum)
#define MMAF16(ac, a, b0, b1) \
    asm volatile("mma.sync.aligned.m16n8k16.row.col.f16.f16.f16.f16 " \
        "{%0,%1},{%2,%3,%4,%5},{%6,%7},{%0,%1};" \
        : "+r"((ac)[0]), "+r"((ac)[1]) \
        : "r"((a)[0]), "r"((a)[1]), "r"((a)[2]), "r"((a)[3]), "r"(b0), "r"(b1))

// SMEM: 2 stages, each A[128][128B] + B[256][128B]
#define A_BYTES     (TILE_N * 128)            // 16384
#define B_BYTES     (TILE_M * 128)            // 32768
#define STAGE_BYTES (A_BYTES + B_BYTES)       // 49152
#define SM_A(s)     ((s) * STAGE_BYTES)
#define SM_B(s)     (SM_A(s) + A_BYTES)
#define SMEM_TOTAL  (2 * STAGE_BYTES)         // 98304

__device__ __forceinline__ unsigned pack2_f16(float a, float b) {
    unsigned short ua = __half_as_ushort(__float2half_rn(a));
    unsigned short ub = __half_as_ushort(__float2half_rn(b));
    return (unsigned)ua | ((unsigned)ub << 16);
}

// ---------------------------------------------------------------------------
// Normalize rows -> fp32 + packed f16 copies. One warp per row. Resets g_cnt.
// ---------------------------------------------------------------------------
__global__ void __launch_bounds__(256) normsplit_kernel(
    const float* __restrict__ Ex, const float* __restrict__ Ey, int N, int M)
{
    if (blockIdx.x == 0 && threadIdx.x == 0) g_cnt = 0;

    int warp = threadIdx.x >> 5, lane = threadIdx.x & 31;
    int row = blockIdx.x * 8 + warp;
    if (row >= N + M) return;

    const float* src; float* dstf; unsigned* dsth; int r;
    if (row < N) { src = Ex; dstf = g_xn; dsth = g_xh; r = row; }
    else         { src = Ey; dstf = g_yn; dsth = g_yh; r = row - N; }

    const float4* s4 = reinterpret_cast<const float4*>(src + (size_t)r * D);
    float4 v0 = s4[lane];
    float4 v1 = s4[lane + 32];

    float ss = v0.x*v0.x + v0.y*v0.y + v0.z*v0.z + v0.w*v0.w
             + v1.x*v1.x + v1.y*v1.y + v1.z*v1.z + v1.w*v1.w;
    #pragma unroll
    for (int off = 16; off > 0; off >>= 1)
        ss += __shfl_xor_sync(0xFFFFFFFFu, ss, off);
    float inv = 1.0f / fmaxf(sqrtf(ss), 1e-8f);

    v0.x *= inv; v0.y *= inv; v0.z *= inv; v0.w *= inv;
    v1.x *= inv; v1.y *= inv; v1.z *= inv; v1.w *= inv;

    float4* d4 = reinterpret_cast<float4*>(dstf + (size_t)r * D);
    d4[lane]      = v0;
    d4[lane + 32] = v1;

    // f16 row: 128 u32 per row; v0 -> ints [2*lane, 2*lane+1], v1 -> +64
    unsigned* dh = dsth + (size_t)r * (D/2);
    dh[2*lane]          = pack2_f16(v0.x, v0.y);
    dh[2*lane + 1]      = pack2_f16(v0.z, v0.w);
    dh[2*lane + 64]     = pack2_f16(v1.x, v1.y);
    dh[2*lane + 65]     = pack2_f16(v1.z, v1.w);
}

// ---------------------------------------------------------------------------
// Screen: f16 HMMA GEMM with f16 accumulate, emit pairs cos_f16 > 0.24.
// CTA 128(n) x 256(m); 16 warps, warp tile 64(n) x 32(m); K=256 f16 in
// 4 chunks of 64, 2-stage cp.async pipeline.
// ---------------------------------------------------------------------------
__global__ void __launch_bounds__(NT, 1) screen_kernel()
{
    extern __shared__ __align__(1024) char smem[];
    const uint32_t sb = smem_u32(smem);
    const int t = threadIdx.x;
    const int wid = t >> 5, lane = t & 31;
    const int nBase = blockIdx.y * TILE_N;
    const int mBase = blockIdx.x * TILE_M;
    const int nOff = (wid >> 3) * 64;     // 2 warp-rows
    const int mOff = (wid & 7) * 32;      // 8 warp-cols

    const char* Xp = (const char*)g_xh + (size_t)nBase * 512;   // 512 B/row
    const char* Yp = (const char*)g_yh + (size_t)mBase * 512;

    // acc[mi][n8 block][2 regs], each reg = f16x2 (2 m-cols)
    uint32_t acc[4][4][2];
    #pragma unroll
    for (int mi = 0; mi < 4; mi++)
        #pragma unroll
        for (int j = 0; j < 4; j++) { acc[mi][j][0] = 0u; acc[mi][j][1] = 0u; }

    // Loader for chunk c into stage s: A 1024x16B, B 2048x16B over 512 threads
    #define LOAD_CHUNK(c, s) do {                                              \
        int bkb = (c) * BKB;                                                   \
        _Pragma("unroll")                                                      \
        for (int i = 0; i < 2; i++) {                                          \
            int idx = t + 512 * i; int r = idx >> 3; int kb = (idx & 7) * 16;  \
            cp16(sb + SM_A(s) + SWZ(r * 128 + kb),                             \
                 Xp + (size_t)r * 512 + bkb + kb);                             \
        }                                                                      \
        _Pragma("unroll")                                                      \
        for (int i = 0; i < 4; i++) {                                          \
            int idx = t + 512 * i; int r = idx >> 3; int kb = (idx & 7) * 16;  \
            cp16(sb + SM_B(s) + SWZ(r * 128 + kb),                             \
                 Yp + (size_t)r * 512 + bkb + kb);                             \
        }                                                                      \
        CP_COMMIT();                                                           \
    } while (0)

    LOAD_CHUNK(0, 0);
    LOAD_CHUNK(1, 1);

    // ldmatrix lane addressing (HW-verified layout from R4/R5)
    const int lrow = (lane & 7) + ((lane >> 3) & 1) * 8;
    const int lkb  = (lane >> 4) * 16;

    for (int c = 0; c < NCHUNK; c++) {
        if (c < NCHUNK - 1) CP_WAIT(1); else CP_WAIT(0);
        __syncthreads();
        const int s = c & 1;

        #pragma unroll
        for (int kk = 0; kk < 4; kk++) {          // 4 x k16 per 128B chunk
            uint32_t af[4][4], bf[2][4];
            #pragma unroll
            for (int mi = 0; mi < 4; mi++) {
                uint32_t addr = sb + SM_A(s)
                    + SWZ((nOff + mi * 16 + lrow) * 128 + kk * 32 + lkb);
                LDSM4(af[mi], addr);
            }
            #pragma unroll
            for (int nj = 0; nj < 2; nj++) {
                uint32_t addr = sb + SM_B(s)
                    + SWZ((mOff + nj * 16 + lrow) * 128 + kk * 32 + lkb);
                LDSM4(bf[nj], addr);
            }
            #pragma unroll
            for (int mi = 0; mi < 4; mi++)
                #pragma unroll
                for (int nj = 0; nj < 2; nj++) {
                    MMAF16(acc[mi][2*nj],     af[mi], bf[nj][0], bf[nj][2]);
                    MMAF16(acc[mi][2*nj + 1], af[mi], bf[nj][1], bf[nj][3]);
                }
        }
        __syncthreads();
        if (c + 2 < NCHUNK) LOAD_CHUNK(c + 2, s);
    }

    // Emit candidates. reg r: rows lane>>2 (+8 for r=1); cols 2(lane&3)+{0,1}
    const int rBase = nBase + nOff + (lane >> 2);
    const int cBase = mBase + mOff + 2 * (lane & 3);
    #pragma unroll
    for (int mi = 0; mi < 4; mi++)
        #pragma unroll
        for (int j = 0; j < 4; j++)
            #pragma unroll
            for (int r = 0; r < 2; r++) {
                __half2 h = *reinterpret_cast<__half2*>(&acc[mi][j][r]);
                float c0 = __low2float(h), c1 = __high2float(h);
                if (c0 > SCREEN_T) {
                    int idx = atomicAdd(&g_cnt, 1);
                    if (idx < CAP)
                        g_pairs[idx] = make_int2(rBase + mi*16 + r*8, cBase + j*8);
                }
                if (c1 > SCREEN_T) {
                    int idx = atomicAdd(&g_cnt, 1);
                    if (idx < CAP)
                        g_pairs[idx] = make_int2(rBase + mi*16 + r*8, cBase + j*8 + 1);
                }
            }
    #undef LOAD_CHUNK
}

// ---------------------------------------------------------------------------
// Exact fp32 recompute of candidates: dot + expf + atomicAdd. 1 warp/pair.
// ---------------------------------------------------------------------------
__global__ void __launch_bounds__(256) recompute_kernel(float* __restrict__ out)
{
    int lane = threadIdx.x & 31;
    int w    = (blockIdx.x * blockDim.x + threadIdx.x) >> 5;
    int nw   = (gridDim.x * blockDim.x) >> 5;
    int cnt  = *(volatile int*)&g_cnt;
    if (cnt > CAP) cnt = CAP;

    for (int i = w; i < cnt; i += nw) {
        int2 p = g_pairs[i];
        const float4* x = reinterpret_cast<const float4*>(g_xn + (size_t)p.x * D);
        const float4* y = reinterpret_cast<const float4*>(g_yn + (size_t)p.y * D);
        float4 xa = x[lane], xb = x[lane + 32];
        float4 ya = y[lane], yb = y[lane + 32];
        float s = xa.x*ya.x + xa.y*ya.y + xa.z*ya.z + xa.w*ya.w
                + xb.x*yb.x + xb.y*yb.y + xb.z*yb.z + xb.w*yb.w;
        #pragma unroll
        for (int off = 16; off > 0; off >>= 1)
            s += __shfl_xor_sync(0xFFFFFFFFu, s, off);
        if (lane == 0) {
            float dd = s - 1.0f;
            float e = expf(LOG_NORM - HALF_INV_SIG2 * dd * dd);
            if (e != 0.0f) atomicAdd(&out[p.y], e);
        }
    }
}

// ---------------------------------------------------------------------------
extern "C" void kernel_launch(void* const* d_in, const int* in_sizes, int n_in,
                              void* d_out, int out_size)
{
    const float* Ex = (const float*)d_in[0];
    const float* Ey = (const float*)d_in[1];
    float* out = (float*)d_out;

    int N = in_sizes[0] / D;   // 8192
    int M = in_sizes[1] / D;   // 8192

    cudaFuncSetAttribute(screen_kernel,
                         cudaFuncAttributeMaxDynamicSharedMemorySize, SMEM_TOTAL);

    cudaMemsetAsync(out, 0, (size_t)out_size * sizeof(float));

    normsplit_kernel<<<(N + M + 7) / 8, 256>>>(Ex, Ey, N, M);

    dim3 grid(M / TILE_M, N / TILE_N);
    screen_kernel<<<grid, NT, SMEM_TOTAL>>>();

    recompute_kernel<<<64, 256>>>(out);
}